// round 3
// baseline (speedup 1.0000x reference)
#include <cuda_runtime.h>
#include <cuda_bf16.h>

#define N_NODES 50000
#define N_EDGES 800000
#define D       64
#define ROWS    128        // rows per block in the dense kernel
#define SCAN_T  1024
#define CHUNK   49         // 1024*49 = 50176 >= N_NODES

// Scratch (__device__ globals; zero-initialized at module load).
// Invariant: g_cnt is all-zero on entry to kernel_launch (scan_kernel restores it).
__device__ int   g_cnt[N_NODES];
__device__ int   g_off[N_NODES + 1];
__device__ int   g_ctr[N_NODES];
__device__ int   g_ssrc[N_EDGES];
__device__ float g_sw[N_EDGES];
__device__ float g_neigh[N_NODES * D];

// ---------------------------------------------------------------------------
// K1: histogram of edge destinations
// ---------------------------------------------------------------------------
__global__ void hist_kernel(const int* __restrict__ dst) {
    int t = blockIdx.x * blockDim.x + threadIdx.x;
    if (t < N_EDGES) atomicAdd(&g_cnt[dst[t]], 1);
}

// ---------------------------------------------------------------------------
// K2: single-block exclusive scan: counts -> offsets (+ working counters),
// then re-zero counts (keeps the zero-invariant across graph replays).
// ---------------------------------------------------------------------------
__global__ __launch_bounds__(SCAN_T)
void scan_kernel() {
    __shared__ int ssum[SCAN_T];
    int t = threadIdx.x;
    int base = t * CHUNK;

    int run = 0;
    for (int i = 0; i < CHUNK; i++) {
        int idx = base + i;
        if (idx < N_NODES) run += g_cnt[idx];
    }
    ssum[t] = run;
    __syncthreads();

    // Hillis-Steele inclusive scan
    for (int off = 1; off < SCAN_T; off <<= 1) {
        int v = (t >= off) ? ssum[t - off] : 0;
        __syncthreads();
        ssum[t] += v;
        __syncthreads();
    }
    int prefix = (t > 0) ? ssum[t - 1] : 0;

    int acc = prefix;
    for (int i = 0; i < CHUNK; i++) {
        int idx = base + i;
        if (idx < N_NODES) {
            int c = g_cnt[idx];
            g_off[idx] = acc;
            g_ctr[idx] = acc;
            g_cnt[idx] = 0;        // restore invariant
            acc += c;
        }
    }
    if (t == SCAN_T - 1) g_off[N_NODES] = acc;   // == N_EDGES
}

// ---------------------------------------------------------------------------
// K3: reorder edges into dst-sorted order (counting-sort scatter phase)
// ---------------------------------------------------------------------------
__global__ void reorder_kernel(const int*   __restrict__ src,
                               const int*   __restrict__ dst,
                               const float* __restrict__ w) {
    int t = blockIdx.x * blockDim.x + threadIdx.x;
    if (t >= N_EDGES) return;
    int d = dst[t];
    int p = atomicAdd(&g_ctr[d], 1);
    g_ssrc[p] = src[t];
    g_sw[p]   = w[t];
}

// ---------------------------------------------------------------------------
// K4: gather-side segment reduce. One warp per node; lane l owns dims
// 2l, 2l+1. Edge meta loaded 32-at-a-time and broadcast via shfl; each
// edge costs one coalesced 256B/warp row read. Single non-atomic write.
// ---------------------------------------------------------------------------
__global__ void gather_kernel(const float* __restrict__ h) {
    int warp = (blockIdx.x * blockDim.x + threadIdx.x) >> 5;
    int lane = threadIdx.x & 31;
    if (warp >= N_NODES) return;

    int beg = g_off[warp];
    int end = g_off[warp + 1];

    float2 acc = make_float2(0.f, 0.f);

    for (int e0 = beg; e0 < end; e0 += 32) {
        int n = min(32, end - e0);
        int   s  = 0;
        float wv = 0.f;
        if (lane < n) {
            s  = g_ssrc[e0 + lane];
            wv = g_sw[e0 + lane];
        }
        for (int j = 0; j < n; j++) {
            int   ss = __shfl_sync(0xffffffffu, s,  j);
            float ww = __shfl_sync(0xffffffffu, wv, j);
            float2 hv = *reinterpret_cast<const float2*>(h + (size_t)ss * D + 2 * lane);
            acc.x = fmaf(ww, hv.x, acc.x);
            acc.y = fmaf(ww, hv.y, acc.y);
        }
    }
    *reinterpret_cast<float2*>(g_neigh + (size_t)warp * D + 2 * lane) = acc;
}

// ---------------------------------------------------------------------------
// K5: dense  out = relu([h | neigh] @ [W_self | W_neigh]^T + b_self + b_neigh)
// (round-1 version: plain FFMA, broadcast LDS.128 weights, padded sX)
// ---------------------------------------------------------------------------
__global__ __launch_bounds__(ROWS)
void dense_kernel(const float* __restrict__ h,
                  const float* __restrict__ Ws, const float* __restrict__ bs,
                  const float* __restrict__ Wn, const float* __restrict__ bn,
                  float* __restrict__ out) {
    __shared__ __align__(16) float sW[128 * 64];  // sW[k*64+j]
    __shared__ float sX[32][ROWS + 1];
    __shared__ float sB[64];

    const int tid     = threadIdx.x;
    const int rowBase = blockIdx.x * ROWS;
    const int row     = rowBase + tid;
    const bool valid  = row < N_NODES;

    for (int idx = tid; idx < 128 * 64; idx += ROWS) {
        int k = idx >> 6, j = idx & 63;
        sW[idx] = (k < 64) ? Ws[j * 64 + k] : Wn[j * 64 + (k - 64)];
    }
    if (tid < 64) sB[tid] = bs[tid] + bn[tid];

    float acc[64];
#pragma unroll
    for (int j = 0; j < 64; j++) acc[j] = 0.f;

    const int lane = tid & 31;
    const int rq   = tid >> 5;

    for (int kc = 0; kc < 4; kc++) {
        const float* srcp = (kc < 2) ? h : g_neigh;
        const int colBase = (kc & 1) * 32;

        __syncthreads();

        for (int r = rq; r < ROWS; r += ROWS / 32) {
            int rr = rowBase + r;
            float val = (rr < N_NODES) ? srcp[(size_t)rr * D + colBase + lane] : 0.f;
            sX[lane][r] = val;
        }
        __syncthreads();

        const float4* sW4 = reinterpret_cast<const float4*>(sW) + kc * 32 * 16;
#pragma unroll 4
        for (int kk = 0; kk < 32; kk++) {
            float x = sX[kk][tid];
            const float4* wrow = sW4 + kk * 16;
#pragma unroll
            for (int j4 = 0; j4 < 16; j4++) {
                float4 wv = wrow[j4];
                acc[4 * j4 + 0] = fmaf(x, wv.x, acc[4 * j4 + 0]);
                acc[4 * j4 + 1] = fmaf(x, wv.y, acc[4 * j4 + 1]);
                acc[4 * j4 + 2] = fmaf(x, wv.z, acc[4 * j4 + 2]);
                acc[4 * j4 + 3] = fmaf(x, wv.w, acc[4 * j4 + 3]);
            }
        }
    }

    if (valid) {
        float4* op = reinterpret_cast<float4*>(out + (size_t)row * D);
#pragma unroll
        for (int j4 = 0; j4 < 16; j4++) {
            float4 o;
            o.x = fmaxf(acc[4 * j4 + 0] + sB[4 * j4 + 0], 0.f);
            o.y = fmaxf(acc[4 * j4 + 1] + sB[4 * j4 + 1], 0.f);
            o.z = fmaxf(acc[4 * j4 + 2] + sB[4 * j4 + 2], 0.f);
            o.w = fmaxf(acc[4 * j4 + 3] + sB[4 * j4 + 3], 0.f);
            op[j4] = o;
        }
    }
}

// ---------------------------------------------------------------------------
// kernel_launch
//   0: h [N,D] f32   1: edge_src [E] i32   2: edge_dst [E] i32   3: edge_w [E] f32
//   4: W_self [D,D]  5: b_self [D]         6: W_neigh [D,D]      7: b_neigh [D]
// ---------------------------------------------------------------------------
extern "C" void kernel_launch(void* const* d_in, const int* in_sizes, int n_in,
                              void* d_out, int out_size) {
    const float* h        = (const float*)d_in[0];
    const int*   edge_src = (const int*)  d_in[1];
    const int*   edge_dst = (const int*)  d_in[2];
    const float* edge_w   = (const float*)d_in[3];
    const float* W_self   = (const float*)d_in[4];
    const float* b_self   = (const float*)d_in[5];
    const float* W_neigh  = (const float*)d_in[6];
    const float* b_neigh  = (const float*)d_in[7];
    float* out = (float*)d_out;

    const int eb = (N_EDGES + 255) / 256;

    hist_kernel<<<eb, 256>>>(edge_dst);
    scan_kernel<<<1, SCAN_T>>>();
    reorder_kernel<<<eb, 256>>>(edge_src, edge_dst, edge_w);

    {
        int warpsPerBlock = 8;                    // 256 threads
        int blocks = (N_NODES + warpsPerBlock - 1) / warpsPerBlock;
        gather_kernel<<<blocks, warpsPerBlock * 32>>>(h);
    }

    {
        int blocks = (N_NODES + ROWS - 1) / ROWS;
        dense_kernel<<<blocks, ROWS>>>(h, W_self, b_self, W_neigh, b_neigh, out);
    }
}

// round 4
// speedup vs baseline: 1.8741x; 1.8741x over previous
#include <cuda_runtime.h>
#include <cuda_bf16.h>

#define N_NODES 50000
#define N_EDGES 800000
#define D       64
#define ROWS    128                    // rows per block in the dense kernel
#define SBLK    1024                   // scan block size
#define NSB     ((N_NODES + SBLK - 1) / SBLK)   // 49 scan blocks

// Scratch (__device__ globals; zero-initialized at module load).
// Invariant: g_cnt is all-zero on entry (scan pass 3 restores it).
__device__ int   g_cnt[N_NODES];
__device__ int   g_off[N_NODES + 1];
__device__ int   g_ctr[N_NODES];
__device__ int   g_bsum[NSB];
__device__ int   g_bofs[NSB];
__device__ int2  g_edge[N_EDGES];      // {src, float_as_int(w)} sorted by dst
__device__ float g_neigh[N_NODES * D];

// ---------------------------------------------------------------------------
// K1: histogram of edge destinations (spread atomics, L2-resident)
// ---------------------------------------------------------------------------
__global__ void hist_kernel(const int* __restrict__ dst) {
    int t = blockIdx.x * blockDim.x + threadIdx.x;
    if (t < N_EDGES) atomicAdd(&g_cnt[dst[t]], 1);
}

// ---------------------------------------------------------------------------
// K2a: per-block sums of g_cnt (coalesced) -> g_bsum
// ---------------------------------------------------------------------------
__global__ __launch_bounds__(SBLK)
void scan_bsum_kernel() {
    __shared__ int s[SBLK];
    int t = threadIdx.x;
    int idx = blockIdx.x * SBLK + t;
    s[t] = (idx < N_NODES) ? g_cnt[idx] : 0;
    __syncthreads();
    for (int off = SBLK / 2; off > 0; off >>= 1) {
        if (t < off) s[t] += s[t + off];
        __syncthreads();
    }
    if (t == 0) g_bsum[blockIdx.x] = s[0];
}

// ---------------------------------------------------------------------------
// K2b: exclusive scan of the NSB block sums (tiny; smem-resident)
// ---------------------------------------------------------------------------
__global__ void scan_tops_kernel() {
    __shared__ int s[NSB];
    int t = threadIdx.x;
    if (t < NSB) s[t] = g_bsum[t];
    __syncthreads();
    if (t == 0) {
        int acc = 0;
        for (int i = 0; i < NSB; i++) { int c = s[i]; s[i] = acc; acc += c; }
    }
    __syncthreads();
    if (t < NSB) g_bofs[t] = s[t];
}

// ---------------------------------------------------------------------------
// K2c: per-block exclusive scan (Hillis-Steele in smem), add block prefix,
// write offsets + working counters coalesced, re-zero counts.
// ---------------------------------------------------------------------------
__global__ __launch_bounds__(SBLK)
void scan_local_kernel() {
    __shared__ int s[SBLK];
    int t = threadIdx.x;
    int idx = blockIdx.x * SBLK + t;
    int c = (idx < N_NODES) ? g_cnt[idx] : 0;
    s[t] = c;
    __syncthreads();
    // inclusive Hillis-Steele
    for (int off = 1; off < SBLK; off <<= 1) {
        int v = (t >= off) ? s[t - off] : 0;
        __syncthreads();
        s[t] += v;
        __syncthreads();
    }
    int excl = g_bofs[blockIdx.x] + s[t] - c;   // exclusive prefix
    if (idx < N_NODES) {
        g_off[idx] = excl;
        g_ctr[idx] = excl;
        g_cnt[idx] = 0;                         // restore invariant
    }
    if (idx == N_NODES - 1) g_off[N_NODES] = N_EDGES;
}

// ---------------------------------------------------------------------------
// K3: reorder edges into dst-sorted order (counting-sort scatter phase)
// ---------------------------------------------------------------------------
__global__ void reorder_kernel(const int*   __restrict__ src,
                               const int*   __restrict__ dst,
                               const float* __restrict__ w) {
    int t = blockIdx.x * blockDim.x + threadIdx.x;
    if (t >= N_EDGES) return;
    int d = dst[t];
    int p = atomicAdd(&g_ctr[d], 1);
    g_edge[p] = make_int2(src[t], __float_as_int(w[t]));
}

// ---------------------------------------------------------------------------
// K4: gather-side segment reduce. One warp per node; lane l owns dims
// 2l, 2l+1. Edge meta staged 32-at-a-time into per-warp smem (coalesced
// int2 load), then broadcast LDS per edge. One non-atomic row write.
// ---------------------------------------------------------------------------
#define GW 8   // warps per gather block
__global__ __launch_bounds__(GW * 32)
void gather_kernel(const float* __restrict__ h) {
    __shared__ int2 sE[GW][32];
    int wslot = threadIdx.x >> 5;
    int warp  = (blockIdx.x * blockDim.x + threadIdx.x) >> 5;
    int lane  = threadIdx.x & 31;
    if (warp >= N_NODES) return;

    int beg = g_off[warp];
    int end = g_off[warp + 1];

    float2 acc = make_float2(0.f, 0.f);
    const float* hl = h + 2 * lane;

    for (int e0 = beg; e0 < end; e0 += 32) {
        int n = min(32, end - e0);
        if (lane < n) sE[wslot][lane] = g_edge[e0 + lane];
        __syncwarp();
        int j = 0;
        for (; j + 2 <= n; j += 2) {
            int2 ea = sE[wslot][j];
            int2 eb = sE[wslot][j + 1];
            float2 ha = *reinterpret_cast<const float2*>(hl + (size_t)ea.x * D);
            float2 hb = *reinterpret_cast<const float2*>(hl + (size_t)eb.x * D);
            float wa = __int_as_float(ea.y);
            float wb = __int_as_float(eb.y);
            acc.x = fmaf(wa, ha.x, acc.x);
            acc.y = fmaf(wa, ha.y, acc.y);
            acc.x = fmaf(wb, hb.x, acc.x);
            acc.y = fmaf(wb, hb.y, acc.y);
        }
        if (j < n) {
            int2 ea = sE[wslot][j];
            float2 ha = *reinterpret_cast<const float2*>(hl + (size_t)ea.x * D);
            float wa = __int_as_float(ea.y);
            acc.x = fmaf(wa, ha.x, acc.x);
            acc.y = fmaf(wa, ha.y, acc.y);
        }
        __syncwarp();
    }
    *reinterpret_cast<float2*>(g_neigh + (size_t)warp * D + 2 * lane) = acc;
}

// ---------------------------------------------------------------------------
// K5: dense  out = relu([h | neigh] @ [W_self | W_neigh]^T + b_self + b_neigh)
// (round-1 version: plain FFMA, broadcast LDS.128 weights, padded sX)
// ---------------------------------------------------------------------------
__global__ __launch_bounds__(ROWS)
void dense_kernel(const float* __restrict__ h,
                  const float* __restrict__ Ws, const float* __restrict__ bs,
                  const float* __restrict__ Wn, const float* __restrict__ bn,
                  float* __restrict__ out) {
    __shared__ __align__(16) float sW[128 * 64];  // sW[k*64+j]
    __shared__ float sX[32][ROWS + 1];
    __shared__ float sB[64];

    const int tid     = threadIdx.x;
    const int rowBase = blockIdx.x * ROWS;
    const int row     = rowBase + tid;
    const bool valid  = row < N_NODES;

    for (int idx = tid; idx < 128 * 64; idx += ROWS) {
        int k = idx >> 6, j = idx & 63;
        sW[idx] = (k < 64) ? Ws[j * 64 + k] : Wn[j * 64 + (k - 64)];
    }
    if (tid < 64) sB[tid] = bs[tid] + bn[tid];

    float acc[64];
#pragma unroll
    for (int j = 0; j < 64; j++) acc[j] = 0.f;

    const int lane = tid & 31;
    const int rq   = tid >> 5;

    for (int kc = 0; kc < 4; kc++) {
        const float* srcp = (kc < 2) ? h : g_neigh;
        const int colBase = (kc & 1) * 32;

        __syncthreads();

        for (int r = rq; r < ROWS; r += ROWS / 32) {
            int rr = rowBase + r;
            float val = (rr < N_NODES) ? srcp[(size_t)rr * D + colBase + lane] : 0.f;
            sX[lane][r] = val;
        }
        __syncthreads();

        const float4* sW4 = reinterpret_cast<const float4*>(sW) + kc * 32 * 16;
#pragma unroll 4
        for (int kk = 0; kk < 32; kk++) {
            float x = sX[kk][tid];
            const float4* wrow = sW4 + kk * 16;
#pragma unroll
            for (int j4 = 0; j4 < 16; j4++) {
                float4 wv = wrow[j4];
                acc[4 * j4 + 0] = fmaf(x, wv.x, acc[4 * j4 + 0]);
                acc[4 * j4 + 1] = fmaf(x, wv.y, acc[4 * j4 + 1]);
                acc[4 * j4 + 2] = fmaf(x, wv.z, acc[4 * j4 + 2]);
                acc[4 * j4 + 3] = fmaf(x, wv.w, acc[4 * j4 + 3]);
            }
        }
    }

    if (valid) {
        float4* op = reinterpret_cast<float4*>(out + (size_t)row * D);
#pragma unroll
        for (int j4 = 0; j4 < 16; j4++) {
            float4 o;
            o.x = fmaxf(acc[4 * j4 + 0] + sB[4 * j4 + 0], 0.f);
            o.y = fmaxf(acc[4 * j4 + 1] + sB[4 * j4 + 1], 0.f);
            o.z = fmaxf(acc[4 * j4 + 2] + sB[4 * j4 + 2], 0.f);
            o.w = fmaxf(acc[4 * j4 + 3] + sB[4 * j4 + 3], 0.f);
            op[j4] = o;
        }
    }
}

// ---------------------------------------------------------------------------
// kernel_launch
//   0: h [N,D] f32   1: edge_src [E] i32   2: edge_dst [E] i32   3: edge_w [E] f32
//   4: W_self [D,D]  5: b_self [D]         6: W_neigh [D,D]      7: b_neigh [D]
// ---------------------------------------------------------------------------
extern "C" void kernel_launch(void* const* d_in, const int* in_sizes, int n_in,
                              void* d_out, int out_size) {
    const float* h        = (const float*)d_in[0];
    const int*   edge_src = (const int*)  d_in[1];
    const int*   edge_dst = (const int*)  d_in[2];
    const float* edge_w   = (const float*)d_in[3];
    const float* W_self   = (const float*)d_in[4];
    const float* b_self   = (const float*)d_in[5];
    const float* W_neigh  = (const float*)d_in[6];
    const float* b_neigh  = (const float*)d_in[7];
    float* out = (float*)d_out;

    const int eb = (N_EDGES + 255) / 256;

    hist_kernel<<<eb, 256>>>(edge_dst);
    scan_bsum_kernel<<<NSB, SBLK>>>();
    scan_tops_kernel<<<1, 64>>>();
    scan_local_kernel<<<NSB, SBLK>>>();
    reorder_kernel<<<eb, 256>>>(edge_src, edge_dst, edge_w);

    {
        int blocks = (N_NODES + GW - 1) / GW;
        gather_kernel<<<blocks, GW * 32>>>(h);
    }

    {
        int blocks = (N_NODES + ROWS - 1) / ROWS;
        dense_kernel<<<blocks, ROWS>>>(h, W_self, b_self, W_neigh, b_neigh, out);
    }
}